// round 4
// baseline (speedup 1.0000x reference)
#include <cuda_runtime.h>

#define BSZ    1024
#define TSTEPS 128
#define INDIM  256
#define HID    64
#define FREQ   10
#define OUTD   16
#define NW     266     // packed gate cols: i(64) | ste(64) | fre(10) | c(64) | o(64)
#define WPAD   320     // padded N so 5 x 64-col GEMM tiles need no load predicates
#define NB     4       // batch elements per recurrent block

typedef unsigned long long u64;

// Scratch (static device globals; no runtime allocation)
__device__ float d_pre[(size_t)BSZ * TSTEPS * NW];   // (t, b, 266) pre-activations
__device__ float d_Wpack[INDIM * WPAD];              // packed+padded input weights
__device__ float d_bpack[WPAD];                      // packed biases
__device__ float d_cosT[TSTEPS * FREQ];
__device__ float d_sinT[TSTEPS * FREQ];

__device__ __forceinline__ float hsig(float x) {
    return fminf(fmaxf(x * (1.0f / 6.0f) + 0.5f, 0.0f), 1.0f);
}

// ---- packed f32x2 helpers (Blackwell sm_103a; only reachable via PTX) ----
__device__ __forceinline__ u64 pack2f(float lo, float hi) {
    u64 r; asm("mov.b64 %0, {%1, %2};" : "=l"(r) : "f"(lo), "f"(hi)); return r;
}
__device__ __forceinline__ float2 unpack2f(u64 v) {
    float2 r; asm("mov.b64 {%0, %1}, %2;" : "=f"(r.x), "=f"(r.y) : "l"(v)); return r;
}
__device__ __forceinline__ u64 dup2f(float x) { return pack2f(x, x); }
__device__ __forceinline__ u64 fma2(u64 a, u64 b, u64 c) {
    u64 d; asm("fma.rn.f32x2 %0, %1, %2, %3;" : "=l"(d) : "l"(a), "l"(b), "l"(c)); return d;
}
__device__ __forceinline__ u64 mul2(u64 a, u64 b) {
    u64 d; asm("mul.rn.f32x2 %0, %1, %2;" : "=l"(d) : "l"(a), "l"(b)); return d;
}
__device__ __forceinline__ u64 add2(u64 a, u64 b) {
    u64 d; asm("add.rn.f32x2 %0, %1, %2;" : "=l"(d) : "l"(a), "l"(b)); return d;
}

// ---------------- pack input-side weights W_* -> d_Wpack [256 x 320] ----------------
__global__ void pack_w_kernel(const float* __restrict__ W_i,  const float* __restrict__ b_i,
                              const float* __restrict__ W_ste,const float* __restrict__ b_ste,
                              const float* __restrict__ W_fre,const float* __restrict__ b_fre,
                              const float* __restrict__ W_c,  const float* __restrict__ b_c,
                              const float* __restrict__ W_o,  const float* __restrict__ b_o)
{
    int n = blockIdx.x;      // 0..319
    int k = threadIdx.x;     // 0..255
    float w = 0.f, bias = 0.f;
    if (n < 64)       { w = W_i  [k * HID  + n];         bias = b_i  [n]; }
    else if (n < 128) { w = W_ste[k * HID  + (n - 64)];  bias = b_ste[n - 64]; }
    else if (n < 138) { w = W_fre[k * FREQ + (n - 128)]; bias = b_fre[n - 128]; }
    else if (n < 202) { w = W_c  [k * HID  + (n - 138)]; bias = b_c  [n - 138]; }
    else if (n < 266) { w = W_o  [k * HID  + (n - 202)]; bias = b_o  [n - 202]; }
    d_Wpack[k * WPAD + n] = w;
    if (k == 0) d_bpack[n] = bias;
}

// ---------------- trig table, replicating reference fp32 arithmetic ------------------
__global__ void trig_kernel()
{
    int idx = blockIdx.x * blockDim.x + threadIdx.x;   // TSTEPS*FREQ = 1280
    if (idx < TSTEPS * FREQ) {
        int t = idx / FREQ, f = idx % FREQ;
        float fr = (float)f / 10.0f;                               // arange(F)/F in f32
        float omega = (6.28318530717958647692f * (float)(t + 1)) * fr; // (2pi*t)*freq order
        d_cosT[idx] = cosf(omega);
        d_sinT[idx] = sinf(omega);
    }
}

// ---------------- phase 1: pre[t*BS+b][0:266] = x(t,b) @ Wpack + bpack ---------------
// M = T*BS = 131072, K = 256, N = 320(padded). BM=128 BN=64 BK=16, 128 thr,
// per-thread 8(m) x 8(n) tile computed as 8 x 4 packed f32x2 accumulators.
__global__ __launch_bounds__(128) void gemm_kernel(const float* __restrict__ g1)
{
    const int BK = 16;
    __shared__ __align__(16) float As[BK * 132];   // transposed, padded stride
    __shared__ __align__(16) float Bs[BK * 64];

    const int bn = blockIdx.x * 64;     // n-tile fastest -> 5 blocks share A tile in L2
    const int bm = blockIdx.y * 128;
    const int tid = threadIdx.x;
    const int trow = tid >> 3;          // 0..15
    const int tcol = tid & 7;           // 0..7

    // row r = t*BSZ + b ; BM=128 divides BSZ so t is constant per block
    const int t     = bm >> 10;
    const int bbase = bm & 1023;

    u64 acc2[8][4];
    #pragma unroll
    for (int i = 0; i < 8; i++)
        #pragma unroll
        for (int q = 0; q < 4; q++) acc2[i][q] = 0ull;

    for (int kc = 0; kc < INDIM; kc += BK) {
        // A: 128 rows x 16 k, transposed into As[k][m]
        #pragma unroll
        for (int l = 0; l < 4; l++) {
            int idx = tid + l * 128;          // 0..511 float4 slots
            int row = idx >> 2;
            int c4  = (idx & 3) << 2;
            const float4 v = *(const float4*)(g1 +
                ((size_t)(bbase + row) * TSTEPS + t) * INDIM + kc + c4);
            As[(c4 + 0) * 132 + row] = v.x;
            As[(c4 + 1) * 132 + row] = v.y;
            As[(c4 + 2) * 132 + row] = v.z;
            As[(c4 + 3) * 132 + row] = v.w;
        }
        // B: 16 k x 64 n (padded Wpack -> no predicates)
        #pragma unroll
        for (int l = 0; l < 2; l++) {
            int idx = tid + l * 128;          // 0..255 float4 slots
            int k  = idx >> 4;
            int nc = (idx & 15) << 2;
            *(float4*)(&Bs[k * 64 + nc]) =
                *(const float4*)(d_Wpack + (size_t)(kc + k) * WPAD + bn + nc);
        }
        __syncthreads();

        #pragma unroll
        for (int k = 0; k < BK; k++) {
            float4 a0 = *(const float4*)(&As[k * 132 + trow * 8]);
            float4 a1 = *(const float4*)(&As[k * 132 + trow * 8 + 4]);
            ulonglong2 bb0 = *(const ulonglong2*)(&Bs[k * 64 + tcol * 8]);
            ulonglong2 bb1 = *(const ulonglong2*)(&Bs[k * 64 + tcol * 8 + 4]);
            u64 rn2[4] = { bb0.x, bb0.y, bb1.x, bb1.y };
            u64 rm2[8] = { dup2f(a0.x), dup2f(a0.y), dup2f(a0.z), dup2f(a0.w),
                           dup2f(a1.x), dup2f(a1.y), dup2f(a1.z), dup2f(a1.w) };
            #pragma unroll
            for (int i = 0; i < 8; i++)
                #pragma unroll
                for (int q = 0; q < 4; q++)
                    acc2[i][q] = fma2(rm2[i], rn2[q], acc2[i][q]);
        }
        __syncthreads();
    }

    #pragma unroll
    for (int i = 0; i < 8; i++) {
        size_t rrow = (size_t)(bm + trow * 8 + i);
        #pragma unroll
        for (int q = 0; q < 4; q++) {
            float2 fv = unpack2f(acc2[i][q]);
            int n = bn + tcol * 8 + 2 * q;
            if (n < NW)     d_pre[rrow * NW + n]     = fv.x + d_bpack[n];
            if (n + 1 < NW) d_pre[rrow * NW + n + 1] = fv.y + d_bpack[n + 1];
        }
    }
}

// ---------------- phase 2: sequential scan, 1 block (64 thr) per 4 batch elements ----
// U matrices used in ORIGINAL [k][j] layout: per k, lanes j read consecutive floats
// (one 128B line per warp per LDG). Each U value feeds 4 batches (2 f32x2 pairs).
__global__ __launch_bounds__(64) void recurrent_kernel(
    const float* __restrict__ U_i, const float* __restrict__ U_ste,
    const float* __restrict__ U_c, const float* __restrict__ U_o,
    const float* __restrict__ U_fre,
    const float* __restrict__ U_a, const float* __restrict__ b_a,
    const float* __restrict__ W_p, const float* __restrict__ b_p,
    const float* __restrict__ fc_w, const float* __restrict__ fc_b,
    float* __restrict__ out)
{
    const int j  = threadIdx.x;          // hidden unit owned by this thread
    const int b0 = blockIdx.x * NB;      // 4 consecutive batch elements

    __shared__ __align__(16) u64 sh_ha[HID];   // h pairs (b0,b1)
    __shared__ __align__(16) u64 sh_hb[HID];   // h pairs (b2,b3)
    __shared__ u64 sh_frea[FREQ], sh_freb[FREQ];
    __shared__ float sh_ct[FREQ], sh_st[FREQ];
    __shared__ float2 sh_red[2][2];

    u64 SreA[FREQ], SimA[FREQ], SreB[FREQ], SimB[FREQ];
    #pragma unroll
    for (int f = 0; f < FREQ; f++) { SreA[f]=0ull; SimA[f]=0ull; SreB[f]=0ull; SimB[f]=0ull; }

    float ua[FREQ];
    #pragma unroll
    for (int f = 0; f < FREQ; f++) ua[f] = U_a[f];
    const float ba = b_a[j];

    sh_ha[j] = 0ull; sh_hb[j] = 0ull;
    __syncthreads();

    u64 hnA = 0ull, hnB = 0ull;

    for (int t = 0; t < TSTEPS; t++) {
        const float* r = d_pre + ((size_t)t * BSZ + b0) * NW;
        // pre-activation loads: issued up front, consumed after the GEMV (latency hidden)
        float pi0 = r[j],          pi1 = r[NW + j],          pi2 = r[2*NW + j],          pi3 = r[3*NW + j];
        float ps0 = r[64 + j],     ps1 = r[NW + 64 + j],     ps2 = r[2*NW + 64 + j],     ps3 = r[3*NW + 64 + j];
        float pc0 = r[138 + j],    pc1 = r[NW + 138 + j],    pc2 = r[2*NW + 138 + j],    pc3 = r[3*NW + 138 + j];
        float po0 = r[202 + j],    po1 = r[NW + 202 + j],    po2 = r[2*NW + 202 + j],    po3 = r[3*NW + 202 + j];

        u64 aiA=0ull, aiB=0ull, asA=0ull, asB=0ull, acA=0ull, acB=0ull, aoA=0ull, aoB=0ull;

        #pragma unroll
        for (int k4 = 0; k4 < 16; k4++) {
            ulonglong2 p0 = *(const ulonglong2*)(sh_ha + k4 * 4);
            ulonglong2 p1 = *(const ulonglong2*)(sh_ha + k4 * 4 + 2);
            ulonglong2 q0 = *(const ulonglong2*)(sh_hb + k4 * 4);
            ulonglong2 q1 = *(const ulonglong2*)(sh_hb + k4 * 4 + 2);
            u64 hA[4] = { p0.x, p0.y, p1.x, p1.y };
            u64 hB[4] = { q0.x, q0.y, q1.x, q1.y };
            #pragma unroll
            for (int kk = 0; kk < 4; kk++) {
                int k = k4 * 4 + kk;
                u64 u;
                u = dup2f(__ldg(U_i   + k * HID + j));
                aiA = fma2(hA[kk], u, aiA); aiB = fma2(hB[kk], u, aiB);
                u = dup2f(__ldg(U_ste + k * HID + j));
                asA = fma2(hA[kk], u, asA); asB = fma2(hB[kk], u, asB);
                u = dup2f(__ldg(U_c   + k * HID + j));
                acA = fma2(hA[kk], u, acA); acB = fma2(hB[kk], u, acB);
                u = dup2f(__ldg(U_o   + k * HID + j));
                aoA = fma2(hA[kk], u, aoA); aoB = fma2(hB[kk], u, aoB);
            }
        }

        // fre gates: only lanes 0..9 of warp 0 (warp 1 skips entirely)
        if (j < FREQ) {
            float pf0 = r[128 + j], pf1 = r[NW + 128 + j];
            float pf2 = r[2*NW + 128 + j], pf3 = r[3*NW + 128 + j];
            u64 afA = 0ull, afB = 0ull;
            #pragma unroll
            for (int k4 = 0; k4 < 16; k4++) {
                ulonglong2 p0 = *(const ulonglong2*)(sh_ha + k4 * 4);
                ulonglong2 p1 = *(const ulonglong2*)(sh_ha + k4 * 4 + 2);
                ulonglong2 q0 = *(const ulonglong2*)(sh_hb + k4 * 4);
                ulonglong2 q1 = *(const ulonglong2*)(sh_hb + k4 * 4 + 2);
                u64 hA[4] = { p0.x, p0.y, p1.x, p1.y };
                u64 hB[4] = { q0.x, q0.y, q1.x, q1.y };
                #pragma unroll
                for (int kk = 0; kk < 4; kk++) {
                    int k = k4 * 4 + kk;
                    u64 u = dup2f(__ldg(U_fre + k * FREQ + j));
                    afA = fma2(hA[kk], u, afA); afB = fma2(hB[kk], u, afB);
                }
            }
            float2 fa = unpack2f(add2(afA, pack2f(pf0, pf1)));
            float2 fb = unpack2f(add2(afB, pack2f(pf2, pf3)));
            sh_frea[j] = pack2f(hsig(fa.x), hsig(fa.y));
            sh_freb[j] = pack2f(hsig(fb.x), hsig(fb.y));
            sh_ct[j] = d_cosT[t * FREQ + j];
            sh_st[j] = d_sinT[t * FREQ + j];
        }

        // gate activations (exact scalar fp32, matches reference)
        float2 v;
        v = unpack2f(add2(aiA, pack2f(pi0, pi1)));  float gi0 = hsig(v.x), gi1 = hsig(v.y);
        v = unpack2f(add2(aiB, pack2f(pi2, pi3)));  float gi2 = hsig(v.x), gi3 = hsig(v.y);
        v = unpack2f(add2(asA, pack2f(ps0, ps1)));  float gs0 = hsig(v.x), gs1 = hsig(v.y);
        v = unpack2f(add2(asB, pack2f(ps2, ps3)));  float gs2 = hsig(v.x), gs3 = hsig(v.y);
        v = unpack2f(add2(acA, pack2f(pc0, pc1)));  float cc0 = gi0 * tanhf(v.x), cc1 = gi1 * tanhf(v.y);
        v = unpack2f(add2(acB, pack2f(pc2, pc3)));  float cc2 = gi2 * tanhf(v.x), cc3 = gi3 * tanhf(v.y);
        v = unpack2f(add2(aoA, pack2f(po0, po1)));  float go0 = hsig(v.x), go1 = hsig(v.y);
        v = unpack2f(add2(aoB, pack2f(po2, po3)));  float go2 = hsig(v.x), go3 = hsig(v.y);

        u64 ccA = pack2f(cc0, cc1), ccB = pack2f(cc2, cc3);
        u64 gsA = pack2f(gs0, gs1), gsB = pack2f(gs2, gs3);

        __syncthreads();   // A: sh_fre/ct/st visible; all sh_h reads done

        u64 aaA = pack2f(ba, ba);
        u64 aaB = aaA;
        #pragma unroll
        for (int f = 0; f < FREQ; f++) {
            u64 ctd = dup2f(sh_ct[f]);
            u64 std = dup2f(sh_st[f]);
            u64 uad = dup2f(ua[f]);
            u64 frA = mul2(gsA, sh_frea[f]);
            u64 frB = mul2(gsB, sh_freb[f]);
            SreA[f] = fma2(frA, SreA[f], mul2(ccA, ctd));
            SimA[f] = fma2(frA, SimA[f], mul2(ccA, std));
            SreB[f] = fma2(frB, SreB[f], mul2(ccB, ctd));
            SimB[f] = fma2(frB, SimB[f], mul2(ccB, std));
            u64 ampA = fma2(SimA[f], SimA[f], mul2(SreA[f], SreA[f]));
            u64 ampB = fma2(SimB[f], SimB[f], mul2(SreB[f], SreB[f]));
            aaA = fma2(ampA, uad, aaA);
            aaB = fma2(ampB, uad, aaB);
        }

        float2 a2 = unpack2f(aaA);
        float h0v = go0 * tanhf(a2.x), h1v = go1 * tanhf(a2.y);
        a2 = unpack2f(aaB);
        float h2v = go2 * tanhf(a2.x), h3v = go3 * tanhf(a2.y);
        hnA = pack2f(h0v, h1v);
        hnB = pack2f(h2v, h3v);
        sh_ha[j] = hnA;     // safe: all sh_h reads happened before barrier A
        sh_hb[j] = hnB;
        __syncthreads();   // B: h(t+1) visible for next iteration
    }

    // epilogue: out[b] = fc_b + b_p.fc_w + h . (W_p @ fc_w)
    float vv = 0.f;
    #pragma unroll
    for (int o = 0; o < OUTD; o++) vv = fmaf(W_p[j * OUTD + o], fc_w[o], vv);
    u64 vd = dup2f(vv);
    u64 pA = mul2(hnA, vd), pB = mul2(hnB, vd);
    #pragma unroll
    for (int off = 16; off > 0; off >>= 1) {
        pA = add2(pA, __shfl_down_sync(0xffffffffu, pA, off));
        pB = add2(pB, __shfl_down_sync(0xffffffffu, pB, off));
    }
    if ((j & 31) == 0) {
        sh_red[j >> 5][0] = unpack2f(pA);
        sh_red[j >> 5][1] = unpack2f(pB);
    }
    __syncthreads();
    if (j == 0) {
        float s0 = fc_b[0];
        #pragma unroll
        for (int o = 0; o < OUTD; o++) s0 = fmaf(b_p[o], fc_w[o], s0);
        out[b0 + 0] = s0 + sh_red[0][0].x + sh_red[1][0].x;
        out[b0 + 1] = s0 + sh_red[0][0].y + sh_red[1][0].y;
        out[b0 + 2] = s0 + sh_red[0][1].x + sh_red[1][1].x;
        out[b0 + 3] = s0 + sh_red[0][1].y + sh_red[1][1].y;
    }
}

extern "C" void kernel_launch(void* const* d_in, const int* in_sizes, int n_in,
                              void* d_out, int out_size)
{
    const float* g1    = (const float*)d_in[0];
    const float* W_i   = (const float*)d_in[1];
    const float* U_i   = (const float*)d_in[2];
    const float* b_i   = (const float*)d_in[3];
    const float* W_ste = (const float*)d_in[4];
    const float* U_ste = (const float*)d_in[5];
    const float* b_ste = (const float*)d_in[6];
    const float* W_fre = (const float*)d_in[7];
    const float* U_fre = (const float*)d_in[8];
    const float* b_fre = (const float*)d_in[9];
    const float* W_c   = (const float*)d_in[10];
    const float* U_c   = (const float*)d_in[11];
    const float* b_c   = (const float*)d_in[12];
    const float* W_o   = (const float*)d_in[13];
    const float* U_o   = (const float*)d_in[14];
    const float* b_o   = (const float*)d_in[15];
    const float* U_a   = (const float*)d_in[16];
    const float* b_a   = (const float*)d_in[17];
    const float* W_p   = (const float*)d_in[18];
    const float* b_p   = (const float*)d_in[19];
    const float* fc_w  = (const float*)d_in[20];
    const float* fc_b  = (const float*)d_in[21];

    pack_w_kernel<<<WPAD, 256>>>(W_i, b_i, W_ste, b_ste, W_fre, b_fre,
                                 W_c, b_c, W_o, b_o);
    trig_kernel<<<5, 256>>>();
    gemm_kernel<<<dim3(5, 1024), 128>>>(g1);
    recurrent_kernel<<<BSZ / NB, HID>>>(U_i, U_ste, U_c, U_o, U_fre,
                                        U_a, b_a, W_p, b_p, fc_w, fc_b,
                                        (float*)d_out);
}

// round 5
// speedup vs baseline: 7.4822x; 7.4822x over previous
#include <cuda_runtime.h>

#define BSZ    1024
#define TSTEPS 128
#define INDIM  256
#define HID    64
#define FREQ   10
#define OUTD   16
#define NW     266     // packed gate cols: i(64) | ste(64) | fre(10) | c(64) | o(64)
#define WPAD   320     // padded N so 5 x 64-col GEMM tiles need no load predicates
#define NB     2       // batch elements per recurrent block (one f32x2 pair)

typedef unsigned long long u64;

// Scratch (static device globals; no runtime allocation)
__device__ float d_pre[(size_t)BSZ * TSTEPS * NW];   // (t, b, 266) pre-activations
__device__ float d_Wpack[INDIM * WPAD];              // packed+padded input weights
__device__ float d_bpack[WPAD];                      // packed biases
__device__ float d_Upk[4 * HID * HID];               // interleaved [m][k4][j][kk]
__device__ float d_Ufpk[16 * FREQ * 4];              // interleaved U_fre [k4][j][kk]
__device__ float d_cosT[TSTEPS * FREQ];
__device__ float d_sinT[TSTEPS * FREQ];

__device__ __forceinline__ float hsig(float x) {
    return fminf(fmaxf(x * (1.0f / 6.0f) + 0.5f, 0.0f), 1.0f);
}

// ---- packed f32x2 helpers (Blackwell sm_103a; only reachable via PTX) ----
__device__ __forceinline__ u64 pack2f(float lo, float hi) {
    u64 r; asm("mov.b64 %0, {%1, %2};" : "=l"(r) : "f"(lo), "f"(hi)); return r;
}
__device__ __forceinline__ float2 unpack2f(u64 v) {
    float2 r; asm("mov.b64 {%0, %1}, %2;" : "=f"(r.x), "=f"(r.y) : "l"(v)); return r;
}
__device__ __forceinline__ u64 dup2f(float x) { return pack2f(x, x); }
__device__ __forceinline__ u64 fma2(u64 a, u64 b, u64 c) {
    u64 d; asm("fma.rn.f32x2 %0, %1, %2, %3;" : "=l"(d) : "l"(a), "l"(b), "l"(c)); return d;
}
__device__ __forceinline__ u64 mul2(u64 a, u64 b) {
    u64 d; asm("mul.rn.f32x2 %0, %1, %2;" : "=l"(d) : "l"(a), "l"(b)); return d;
}
__device__ __forceinline__ u64 add2(u64 a, u64 b) {
    u64 d; asm("add.rn.f32x2 %0, %1, %2;" : "=l"(d) : "l"(a), "l"(b)); return d;
}

// ---------------- pack input-side weights W_* -> d_Wpack [256 x 320] ----------------
__global__ void pack_w_kernel(const float* __restrict__ W_i,  const float* __restrict__ b_i,
                              const float* __restrict__ W_ste,const float* __restrict__ b_ste,
                              const float* __restrict__ W_fre,const float* __restrict__ b_fre,
                              const float* __restrict__ W_c,  const float* __restrict__ b_c,
                              const float* __restrict__ W_o,  const float* __restrict__ b_o)
{
    int n = blockIdx.x;      // 0..319
    int k = threadIdx.x;     // 0..255
    float w = 0.f, bias = 0.f;
    if (n < 64)       { w = W_i  [k * HID  + n];         bias = b_i  [n]; }
    else if (n < 128) { w = W_ste[k * HID  + (n - 64)];  bias = b_ste[n - 64]; }
    else if (n < 138) { w = W_fre[k * FREQ + (n - 128)]; bias = b_fre[n - 128]; }
    else if (n < 202) { w = W_c  [k * HID  + (n - 138)]; bias = b_c  [n - 138]; }
    else if (n < 266) { w = W_o  [k * HID  + (n - 202)]; bias = b_o  [n - 202]; }
    d_Wpack[k * WPAD + n] = w;
    if (k == 0) d_bpack[n] = bias;
}

// -------- interleave U so thread j's float4 = U[4*k4 .. 4*k4+3][j] (warp = 512B) ----
__global__ void pack_u_kernel(const float* __restrict__ U_i, const float* __restrict__ U_ste,
                              const float* __restrict__ U_c, const float* __restrict__ U_o,
                              const float* __restrict__ U_fre)
{
    int idx = blockIdx.x * blockDim.x + threadIdx.x;   // 16 x 256 = 4096
    int k4 = idx >> 8, j = (idx >> 2) & 63, kk = idx & 3;
    int k = 4 * k4 + kk;
    d_Upk[0 * 4096 + idx] = U_i  [k * HID + j];
    d_Upk[1 * 4096 + idx] = U_ste[k * HID + j];
    d_Upk[2 * 4096 + idx] = U_c  [k * HID + j];
    d_Upk[3 * 4096 + idx] = U_o  [k * HID + j];
    if (idx < 16 * FREQ * 4) {
        int fk4 = idx / (FREQ * 4), rr = idx % (FREQ * 4);
        int fj = rr >> 2, fkk = rr & 3;
        d_Ufpk[idx] = U_fre[(4 * fk4 + fkk) * FREQ + fj];
    }
}

// ---------------- trig table, replicating reference fp32 arithmetic ------------------
__global__ void trig_kernel()
{
    int idx = blockIdx.x * blockDim.x + threadIdx.x;   // TSTEPS*FREQ = 1280
    if (idx < TSTEPS * FREQ) {
        int t = idx / FREQ, f = idx % FREQ;
        float fr = (float)f / 10.0f;                               // arange(F)/F in f32
        float omega = (6.28318530717958647692f * (float)(t + 1)) * fr; // (2pi*t)*freq order
        d_cosT[idx] = cosf(omega);
        d_sinT[idx] = sinf(omega);
    }
}

// ---------------- phase 1: pre[t*BS+b][0:266] = x(t,b) @ Wpack + bpack ---------------
// M = T*BS = 131072, K = 256, N = 320(padded). BM=128 BN=64 BK=16, 128 thr,
// per-thread 8(m) x 8(n) tile computed as 8 x 4 packed f32x2 accumulators.
__global__ __launch_bounds__(128) void gemm_kernel(const float* __restrict__ g1)
{
    const int BK = 16;
    __shared__ __align__(16) float As[BK * 132];   // transposed, padded stride
    __shared__ __align__(16) float Bs[BK * 64];

    const int bn = blockIdx.x * 64;     // n-tile fastest -> 5 blocks share A tile in L2
    const int bm = blockIdx.y * 128;
    const int tid = threadIdx.x;
    const int trow = tid >> 3;          // 0..15
    const int tcol = tid & 7;           // 0..7

    // row r = t*BSZ + b ; BM=128 divides BSZ so t is constant per block
    const int t     = bm >> 10;
    const int bbase = bm & 1023;

    u64 acc2[8][4];
    #pragma unroll
    for (int i = 0; i < 8; i++)
        #pragma unroll
        for (int q = 0; q < 4; q++) acc2[i][q] = 0ull;

    for (int kc = 0; kc < INDIM; kc += BK) {
        // A: 128 rows x 16 k, transposed into As[k][m]
        #pragma unroll
        for (int l = 0; l < 4; l++) {
            int idx = tid + l * 128;          // 0..511 float4 slots
            int row = idx >> 2;
            int c4  = (idx & 3) << 2;
            const float4 v = *(const float4*)(g1 +
                ((size_t)(bbase + row) * TSTEPS + t) * INDIM + kc + c4);
            As[(c4 + 0) * 132 + row] = v.x;
            As[(c4 + 1) * 132 + row] = v.y;
            As[(c4 + 2) * 132 + row] = v.z;
            As[(c4 + 3) * 132 + row] = v.w;
        }
        // B: 16 k x 64 n (padded Wpack -> no predicates)
        #pragma unroll
        for (int l = 0; l < 2; l++) {
            int idx = tid + l * 128;          // 0..255 float4 slots
            int k  = idx >> 4;
            int nc = (idx & 15) << 2;
            *(float4*)(&Bs[k * 64 + nc]) =
                *(const float4*)(d_Wpack + (size_t)(kc + k) * WPAD + bn + nc);
        }
        __syncthreads();

        #pragma unroll
        for (int k = 0; k < BK; k++) {
            float4 a0 = *(const float4*)(&As[k * 132 + trow * 8]);
            float4 a1 = *(const float4*)(&As[k * 132 + trow * 8 + 4]);
            ulonglong2 bb0 = *(const ulonglong2*)(&Bs[k * 64 + tcol * 8]);
            ulonglong2 bb1 = *(const ulonglong2*)(&Bs[k * 64 + tcol * 8 + 4]);
            u64 rn2[4] = { bb0.x, bb0.y, bb1.x, bb1.y };
            u64 rm2[8] = { dup2f(a0.x), dup2f(a0.y), dup2f(a0.z), dup2f(a0.w),
                           dup2f(a1.x), dup2f(a1.y), dup2f(a1.z), dup2f(a1.w) };
            #pragma unroll
            for (int i = 0; i < 8; i++)
                #pragma unroll
                for (int q = 0; q < 4; q++)
                    acc2[i][q] = fma2(rm2[i], rn2[q], acc2[i][q]);
        }
        __syncthreads();
    }

    #pragma unroll
    for (int i = 0; i < 8; i++) {
        size_t rrow = (size_t)(bm + trow * 8 + i);
        #pragma unroll
        for (int q = 0; q < 4; q++) {
            float2 fv = unpack2f(acc2[i][q]);
            int n = bn + tcol * 8 + 2 * q;
            if (n < NW)     d_pre[rrow * NW + n]     = fv.x + d_bpack[n];
            if (n + 1 < NW) d_pre[rrow * NW + n + 1] = fv.y + d_bpack[n + 1];
        }
    }
}

// ---------------- phase 2: sequential scan, 1 block (64 thr) per 2 batch elements ----
// GEMV uses scalar FFMA (U value broadcast over 2 batches); U loads are float4 over
// the interleaved layout -> each warp LDG.128 covers 512 contiguous bytes (4 lines).
// State update uses packed f32x2 on (b0,b1) pairs.
__global__ __launch_bounds__(64, 6) void recurrent_kernel(
    const float* __restrict__ U_a, const float* __restrict__ b_a,
    const float* __restrict__ W_p, const float* __restrict__ b_p,
    const float* __restrict__ fc_w, const float* __restrict__ fc_b,
    float* __restrict__ out)
{
    const int j  = threadIdx.x;          // hidden unit owned by this thread
    const int b0 = blockIdx.x * NB;

    __shared__ __align__(16) float sh_h0[HID];
    __shared__ __align__(16) float sh_h1[HID];
    __shared__ u64 sh_freP[FREQ];
    __shared__ float sh_ct[FREQ], sh_st[FREQ];
    __shared__ float2 sh_red[2];

    const float4* U0 = (const float4*)d_Upk;           // i
    const float4* U1 = (const float4*)d_Upk + 1024;    // ste
    const float4* U2 = (const float4*)d_Upk + 2048;    // c
    const float4* U3 = (const float4*)d_Upk + 3072;    // o
    const float4* UF = (const float4*)d_Ufpk;
    const float4* H0 = (const float4*)sh_h0;
    const float4* H1 = (const float4*)sh_h1;

    u64 SreP[FREQ], SimP[FREQ];
    #pragma unroll
    for (int f = 0; f < FREQ; f++) { SreP[f] = 0ull; SimP[f] = 0ull; }

    float ua[FREQ];
    #pragma unroll
    for (int f = 0; f < FREQ; f++) ua[f] = U_a[f];
    const float ba = b_a[j];

    sh_h0[j] = 0.f; sh_h1[j] = 0.f;
    __syncthreads();

    float hn0 = 0.f, hn1 = 0.f;

    for (int t = 0; t < TSTEPS; t++) {
        const float* r = d_pre + ((size_t)t * BSZ + b0) * NW;
        // pre-activation loads: issued up front, consumed after the GEMV
        float pi0 = r[j],        pi1 = r[NW + j];
        float ps0 = r[64 + j],   ps1 = r[NW + 64 + j];
        float pc0 = r[138 + j],  pc1 = r[NW + 138 + j];
        float po0 = r[202 + j],  po1 = r[NW + 202 + j];

        float ai0 = 0.f, ai1 = 0.f, as0 = 0.f, as1 = 0.f;
        float ac0 = 0.f, ac1 = 0.f, ao0 = 0.f, ao1 = 0.f;

        #pragma unroll
        for (int k4 = 0; k4 < 16; k4++) {
            float4 h0 = H0[k4];
            float4 h1 = H1[k4];
            float4 u;
            u = U0[k4 * 64 + j];
            ai0 = fmaf(h0.x,u.x,ai0); ai0 = fmaf(h0.y,u.y,ai0);
            ai0 = fmaf(h0.z,u.z,ai0); ai0 = fmaf(h0.w,u.w,ai0);
            ai1 = fmaf(h1.x,u.x,ai1); ai1 = fmaf(h1.y,u.y,ai1);
            ai1 = fmaf(h1.z,u.z,ai1); ai1 = fmaf(h1.w,u.w,ai1);
            u = U1[k4 * 64 + j];
            as0 = fmaf(h0.x,u.x,as0); as0 = fmaf(h0.y,u.y,as0);
            as0 = fmaf(h0.z,u.z,as0); as0 = fmaf(h0.w,u.w,as0);
            as1 = fmaf(h1.x,u.x,as1); as1 = fmaf(h1.y,u.y,as1);
            as1 = fmaf(h1.z,u.z,as1); as1 = fmaf(h1.w,u.w,as1);
            u = U2[k4 * 64 + j];
            ac0 = fmaf(h0.x,u.x,ac0); ac0 = fmaf(h0.y,u.y,ac0);
            ac0 = fmaf(h0.z,u.z,ac0); ac0 = fmaf(h0.w,u.w,ac0);
            ac1 = fmaf(h1.x,u.x,ac1); ac1 = fmaf(h1.y,u.y,ac1);
            ac1 = fmaf(h1.z,u.z,ac1); ac1 = fmaf(h1.w,u.w,ac1);
            u = U3[k4 * 64 + j];
            ao0 = fmaf(h0.x,u.x,ao0); ao0 = fmaf(h0.y,u.y,ao0);
            ao0 = fmaf(h0.z,u.z,ao0); ao0 = fmaf(h0.w,u.w,ao0);
            ao1 = fmaf(h1.x,u.x,ao1); ao1 = fmaf(h1.y,u.y,ao1);
            ao1 = fmaf(h1.z,u.z,ao1); ao1 = fmaf(h1.w,u.w,ao1);
        }

        // fre gates: lanes 0..9 of warp 0 only (warp 1 skips entirely)
        if (j < FREQ) {
            float pf0 = r[128 + j], pf1 = r[NW + 128 + j];
            float af0 = 0.f, af1 = 0.f;
            #pragma unroll
            for (int k4 = 0; k4 < 16; k4++) {
                float4 h0 = H0[k4];
                float4 h1 = H1[k4];
                float4 u = UF[k4 * FREQ + j];
                af0 = fmaf(h0.x,u.x,af0); af0 = fmaf(h0.y,u.y,af0);
                af0 = fmaf(h0.z,u.z,af0); af0 = fmaf(h0.w,u.w,af0);
                af1 = fmaf(h1.x,u.x,af1); af1 = fmaf(h1.y,u.y,af1);
                af1 = fmaf(h1.z,u.z,af1); af1 = fmaf(h1.w,u.w,af1);
            }
            sh_freP[j] = pack2f(hsig(pf0 + af0), hsig(pf1 + af1));
            sh_ct[j] = d_cosT[t * FREQ + j];
            sh_st[j] = d_sinT[t * FREQ + j];
        }

        float gi0 = hsig(pi0 + ai0), gi1 = hsig(pi1 + ai1);
        float gs0 = hsig(ps0 + as0), gs1 = hsig(ps1 + as1);
        float cc0 = gi0 * tanhf(pc0 + ac0), cc1 = gi1 * tanhf(pc1 + ac1);
        float go0 = hsig(po0 + ao0), go1 = hsig(po1 + ao1);

        __syncthreads();   // A: sh_freP/ct/st visible; all sh_h reads done

        u64 ccP = pack2f(cc0, cc1);
        u64 gsP = pack2f(gs0, gs1);
        u64 aaP = pack2f(ba, ba);
        #pragma unroll
        for (int f = 0; f < FREQ; f++) {
            u64 ctd = dup2f(sh_ct[f]);
            u64 std = dup2f(sh_st[f]);
            u64 frP = mul2(gsP, sh_freP[f]);
            SreP[f] = fma2(frP, SreP[f], mul2(ccP, ctd));
            SimP[f] = fma2(frP, SimP[f], mul2(ccP, std));
            u64 ampP = fma2(SimP[f], SimP[f], mul2(SreP[f], SreP[f]));
            aaP = fma2(ampP, dup2f(ua[f]), aaP);
        }

        float2 a2 = unpack2f(aaP);
        hn0 = go0 * tanhf(a2.x);
        hn1 = go1 * tanhf(a2.y);
        sh_h0[j] = hn0;    // safe: all sh_h reads happened before barrier A
        sh_h1[j] = hn1;
        __syncthreads();   // B: h(t+1) visible for next iteration
    }

    // epilogue: out[b] = fc_b + b_p.fc_w + h . (W_p @ fc_w)
    float vv = 0.f;
    #pragma unroll
    for (int o = 0; o < OUTD; o++) vv = fmaf(W_p[j * OUTD + o], fc_w[o], vv);
    u64 pP = mul2(pack2f(hn0, hn1), dup2f(vv));
    #pragma unroll
    for (int off = 16; off > 0; off >>= 1)
        pP = add2(pP, __shfl_down_sync(0xffffffffu, pP, off));
    if ((j & 31) == 0) sh_red[j >> 5] = unpack2f(pP);
    __syncthreads();
    if (j == 0) {
        float s0 = fc_b[0];
        #pragma unroll
        for (int o = 0; o < OUTD; o++) s0 = fmaf(b_p[o], fc_w[o], s0);
        out[b0 + 0] = s0 + sh_red[0].x + sh_red[1].x;
        out[b0 + 1] = s0 + sh_red[0].y + sh_red[1].y;
    }
}

extern "C" void kernel_launch(void* const* d_in, const int* in_sizes, int n_in,
                              void* d_out, int out_size)
{
    const float* g1    = (const float*)d_in[0];
    const float* W_i   = (const float*)d_in[1];
    const float* U_i   = (const float*)d_in[2];
    const float* b_i   = (const float*)d_in[3];
    const float* W_ste = (const float*)d_in[4];
    const float* U_ste = (const float*)d_in[5];
    const float* b_ste = (const float*)d_in[6];
    const float* W_fre = (const float*)d_in[7];
    const float* U_fre = (const float*)d_in[8];
    const float* b_fre = (const float*)d_in[9];
    const float* W_c   = (const float*)d_in[10];
    const float* U_c   = (const float*)d_in[11];
    const float* b_c   = (const float*)d_in[12];
    const float* W_o   = (const float*)d_in[13];
    const float* U_o   = (const float*)d_in[14];
    const float* b_o   = (const float*)d_in[15];
    const float* U_a   = (const float*)d_in[16];
    const float* b_a   = (const float*)d_in[17];
    const float* W_p   = (const float*)d_in[18];
    const float* b_p   = (const float*)d_in[19];
    const float* fc_w  = (const float*)d_in[20];
    const float* fc_b  = (const float*)d_in[21];

    pack_w_kernel<<<WPAD, 256>>>(W_i, b_i, W_ste, b_ste, W_fre, b_fre,
                                 W_c, b_c, W_o, b_o);
    pack_u_kernel<<<16, 256>>>(U_i, U_ste, U_c, U_o, U_fre);
    trig_kernel<<<5, 256>>>();
    gemm_kernel<<<dim3(5, 1024), 128>>>(g1);
    recurrent_kernel<<<BSZ / NB, HID>>>(U_a, b_a, W_p, b_p, fc_w, fc_b,
                                        (float*)d_out);
}

// round 7
// speedup vs baseline: 7.7189x; 1.0316x over previous
#include <cuda_runtime.h>
#include <cuda_bf16.h>
#include <cstdint>

#define BSZ    1024
#define TSTEPS 128
#define INDIM  256
#define HID    64
#define FREQ   10
#define OUTD   16
#define NW     266     // packed gate cols: i(64) | ste(64) | fre(10) | c(64) | o(64)
#define NPAD   288     // padded N: 3 tiles of 96
#define MROWS  (BSZ * TSTEPS)
#define NB     2       // batch elements per recurrent block (one f32x2 pair)

typedef unsigned long long u64;

// ----------------- device globals (no runtime allocation) -----------------
__device__ __align__(16) float d_pre[(size_t)MROWS * NW];   // (t*1024+b, 266) fp32
__device__ __align__(16) __nv_bfloat16 d_Bhi[NPAD * INDIM]; // [n][k] bf16 hi
__device__ __align__(16) __nv_bfloat16 d_Blo[NPAD * INDIM]; // [n][k] bf16 lo
__device__ __align__(8)  float d_bpack[NPAD];
__device__ float d_Upk[4 * HID * HID];                       // interleaved [m][k4][j][kk]
__device__ float d_Ufpk[16 * FREQ * 4];
__device__ float d_cosT[TSTEPS * FREQ];
__device__ float d_sinT[TSTEPS * FREQ];

__device__ __forceinline__ float hsig(float x) {
    return fminf(fmaxf(x * (1.0f / 6.0f) + 0.5f, 0.0f), 1.0f);
}

// ---- packed f32x2 helpers ----
__device__ __forceinline__ u64 pack2f(float lo, float hi) {
    u64 r; asm("mov.b64 %0, {%1, %2};" : "=l"(r) : "f"(lo), "f"(hi)); return r;
}
__device__ __forceinline__ float2 unpack2f(u64 v) {
    float2 r; asm("mov.b64 {%0, %1}, %2;" : "=f"(r.x), "=f"(r.y) : "l"(v)); return r;
}
__device__ __forceinline__ u64 dup2f(float x) { return pack2f(x, x); }
__device__ __forceinline__ u64 fma2(u64 a, u64 b, u64 c) {
    u64 d; asm("fma.rn.f32x2 %0, %1, %2, %3;" : "=l"(d) : "l"(a), "l"(b), "l"(c)); return d;
}
__device__ __forceinline__ u64 mul2(u64 a, u64 b) {
    u64 d; asm("mul.rn.f32x2 %0, %1, %2;" : "=l"(d) : "l"(a), "l"(b)); return d;
}
__device__ __forceinline__ u64 add2(u64 a, u64 b) {
    u64 d; asm("add.rn.f32x2 %0, %1, %2;" : "=l"(d) : "l"(a), "l"(b)); return d;
}

__device__ __forceinline__ uint32_t smem_u32(const void* p) {
    uint32_t a;
    asm("{ .reg .u64 t; cvta.to.shared.u64 t, %1; cvt.u32.u64 %0, t; }" : "=r"(a) : "l"(p));
    return a;
}

// ---- mma.sync helpers (base PTX ISA, no sm_103a feature needed) ----
#define LDSM4(r0, r1, r2, r3, addr) \
    asm volatile("ldmatrix.sync.aligned.m8n8.x4.shared.b16 {%0,%1,%2,%3}, [%4];" \
        : "=r"(r0), "=r"(r1), "=r"(r2), "=r"(r3) : "r"(addr))

#define MMA16816(d, a, b0, b1) \
    asm volatile("mma.sync.aligned.m16n8k16.row.col.f32.bf16.bf16.f32 " \
        "{%0,%1,%2,%3}, {%4,%5,%6,%7}, {%8,%9}, {%0,%1,%2,%3};" \
        : "+f"((d)[0]), "+f"((d)[1]), "+f"((d)[2]), "+f"((d)[3]) \
        : "r"((a)[0]), "r"((a)[1]), "r"((a)[2]), "r"((a)[3]), "r"(b0), "r"(b1))

// ---------------- pack W_* -> Bhi/Blo [288][256] bf16 (+ biases fp32) ---------------
__global__ void pack_w_kernel(const float* __restrict__ W_i,  const float* __restrict__ b_i,
                              const float* __restrict__ W_ste,const float* __restrict__ b_ste,
                              const float* __restrict__ W_fre,const float* __restrict__ b_fre,
                              const float* __restrict__ W_c,  const float* __restrict__ b_c,
                              const float* __restrict__ W_o,  const float* __restrict__ b_o)
{
    int n = blockIdx.x;      // 0..287
    int k = threadIdx.x;     // 0..255
    float w = 0.f, bias = 0.f;
    if (n < 64)       { w = W_i  [k * HID  + n];         bias = b_i  [n]; }
    else if (n < 128) { w = W_ste[k * HID  + (n - 64)];  bias = b_ste[n - 64]; }
    else if (n < 138) { w = W_fre[k * FREQ + (n - 128)]; bias = b_fre[n - 128]; }
    else if (n < 202) { w = W_c  [k * HID  + (n - 138)]; bias = b_c  [n - 138]; }
    else if (n < 266) { w = W_o  [k * HID  + (n - 202)]; bias = b_o  [n - 202]; }
    __nv_bfloat16 h = __float2bfloat16(w);
    __nv_bfloat16 l = __float2bfloat16(w - __bfloat162float(h));
    d_Bhi[n * INDIM + k] = h;
    d_Blo[n * INDIM + k] = l;
    if (k == 0) d_bpack[n] = bias;
}

// -------- interleave U so thread j's float4 = U[4*k4 .. 4*k4+3][j] (warp = 512B) ----
__global__ void pack_u_kernel(const float* __restrict__ U_i, const float* __restrict__ U_ste,
                              const float* __restrict__ U_c, const float* __restrict__ U_o,
                              const float* __restrict__ U_fre)
{
    int idx = blockIdx.x * blockDim.x + threadIdx.x;   // 16 x 256 = 4096
    int k4 = idx >> 8, j = (idx >> 2) & 63, kk = idx & 3;
    int k = 4 * k4 + kk;
    d_Upk[0 * 4096 + idx] = U_i  [k * HID + j];
    d_Upk[1 * 4096 + idx] = U_ste[k * HID + j];
    d_Upk[2 * 4096 + idx] = U_c  [k * HID + j];
    d_Upk[3 * 4096 + idx] = U_o  [k * HID + j];
    if (idx < 16 * FREQ * 4) {
        int fk4 = idx / (FREQ * 4), rr = idx % (FREQ * 4);
        int fj = rr >> 2, fkk = rr & 3;
        d_Ufpk[idx] = U_fre[(4 * fk4 + fkk) * FREQ + fj];
    }
}

// ---------------- trig table, replicating reference fp32 arithmetic ------------------
__global__ void trig_kernel()
{
    int idx = blockIdx.x * blockDim.x + threadIdx.x;   // TSTEPS*FREQ = 1280
    if (idx < TSTEPS * FREQ) {
        int t = idx / FREQ, f = idx % FREQ;
        float fr = (float)f / 10.0f;
        float omega = (6.28318530717958647692f * (float)(t + 1)) * fr;
        d_cosT[idx] = cosf(omega);
        d_sinT[idx] = sinf(omega);
    }
}

// ---------------- phase 1: mma.sync bf16 hi/lo 3-term GEMM --------------------------
// Block 128 thr / 4 warps; tile M=128 x N=96; warp tile 64x48 (4x6 m16n8k16 tiles).
// A (g1 fp32) converted in-kernel to hi/lo bf16 smem tiles; B pre-split in global.
// smem rows stride 40 bf16 (80B) -> conflict-free ldmatrix.
#define SA_HI 0
#define SA_LO 5120
#define SB_HI 10240
#define SB_LO 14080

__global__ __launch_bounds__(128) void gemm_mma_kernel(const float* __restrict__ g1)
{
    __shared__ __align__(16) __nv_bfloat16 sm[17920];

    const int tid  = threadIdx.x;
    const int lane = tid & 31;
    const int wid  = tid >> 5;
    const int n0   = blockIdx.x * 96;
    const int M0   = blockIdx.y * 128;
    const int t     = M0 >> 10;
    const int bbase = M0 & 1023;
    const int wm = (wid & 1) * 64;
    const int wn = (wid >> 1) * 48;

    float d[4][6][4];
    #pragma unroll
    for (int tm = 0; tm < 4; tm++)
        #pragma unroll
        for (int tn = 0; tn < 6; tn++)
            #pragma unroll
            for (int q = 0; q < 4; q++) d[tm][tn][q] = 0.f;

    // ldmatrix lane base addresses
    const int rowA = wm + (lane & 15);
    const int colA = (lane >> 4) * 8;
    const uint32_t uAhi = smem_u32(sm + SA_HI + rowA * 40 + colA);
    const uint32_t uAlo = smem_u32(sm + SA_LO + rowA * 40 + colA);
    const int rowB = wn + ((lane >> 4) * 8) + (lane & 7);
    const int colB = ((lane >> 3) & 1) * 8;
    const uint32_t uBhi = smem_u32(sm + SB_HI + rowB * 40 + colB);
    const uint32_t uBlo = smem_u32(sm + SB_LO + rowB * 40 + colB);

    for (int kc = 0; kc < 8; kc++) {
        __syncthreads();   // previous iteration's fragment reads complete
        // --- A: load g1 fp32 tile (128 x 32), convert to bf16 hi/lo ---
        #pragma unroll
        for (int l = 0; l < 8; l++) {
            int idx = tid + l * 128;          // 0..1023 float4 slots
            int row = idx >> 3, g = idx & 7;
            const float4 v = *(const float4*)(g1 +
                ((size_t)(bbase + row) * TSTEPS + t) * INDIM + kc * 32 + g * 4);
            float xs[4] = {v.x, v.y, v.z, v.w};
            uint32_t hi01, hi23, lo01, lo23;
            __nv_bfloat16 h[4], lo[4];
            #pragma unroll
            for (int i = 0; i < 4; i++) {
                h[i]  = __float2bfloat16(xs[i]);
                lo[i] = __float2bfloat16(xs[i] - __bfloat162float(h[i]));
            }
            hi01 = (uint32_t)__bfloat16_as_ushort(h[0])  | ((uint32_t)__bfloat16_as_ushort(h[1])  << 16);
            hi23 = (uint32_t)__bfloat16_as_ushort(h[2])  | ((uint32_t)__bfloat16_as_ushort(h[3])  << 16);
            lo01 = (uint32_t)__bfloat16_as_ushort(lo[0]) | ((uint32_t)__bfloat16_as_ushort(lo[1]) << 16);
            lo23 = (uint32_t)__bfloat16_as_ushort(lo[2]) | ((uint32_t)__bfloat16_as_ushort(lo[3]) << 16);
            *(uint2*)(sm + SA_HI + row * 40 + g * 4) = make_uint2(hi01, hi23);
            *(uint2*)(sm + SA_LO + row * 40 + g * 4) = make_uint2(lo01, lo23);
        }
        // --- B: copy bf16 hi/lo tile (96 x 32) ---
        #pragma unroll
        for (int l = 0; l < 3; l++) {
            int idx = tid + l * 128;          // 0..383 uint4 slots
            int row = idx >> 2, g = idx & 3;
            *(uint4*)(sm + SB_HI + row * 40 + g * 8) =
                *(const uint4*)(d_Bhi + (size_t)(n0 + row) * INDIM + kc * 32 + g * 8);
            *(uint4*)(sm + SB_LO + row * 40 + g * 8) =
                *(const uint4*)(d_Blo + (size_t)(n0 + row) * INDIM + kc * 32 + g * 8);
        }
        __syncthreads();

        #pragma unroll
        for (int ks = 0; ks < 2; ks++) {
            uint32_t ah[4][4], al[4][4], bh[3][4], bl[3][4];
            #pragma unroll
            for (int tm = 0; tm < 4; tm++) {
                uint32_t off = (uint32_t)(tm * 16 * 40 + ks * 16) * 2;
                LDSM4(ah[tm][0], ah[tm][1], ah[tm][2], ah[tm][3], uAhi + off);
                LDSM4(al[tm][0], al[tm][1], al[tm][2], al[tm][3], uAlo + off);
            }
            #pragma unroll
            for (int jB = 0; jB < 3; jB++) {
                uint32_t off = (uint32_t)(jB * 16 * 40 + ks * 16) * 2;
                LDSM4(bh[jB][0], bh[jB][1], bh[jB][2], bh[jB][3], uBhi + off);
                LDSM4(bl[jB][0], bl[jB][1], bl[jB][2], bl[jB][3], uBlo + off);
            }
            #pragma unroll
            for (int tm = 0; tm < 4; tm++)
                #pragma unroll
                for (int tn = 0; tn < 6; tn++) {
                    int jB = tn >> 1, hh = (tn & 1) * 2;
                    MMA16816(d[tm][tn], ah[tm], bh[jB][hh], bh[jB][hh + 1]);
                    MMA16816(d[tm][tn], ah[tm], bl[jB][hh], bl[jB][hh + 1]);
                    MMA16816(d[tm][tn], al[tm], bh[jB][hh], bh[jB][hh + 1]);
                }
        }
    }

    // --- epilogue: write d_pre with bias, predicated at n < 266 ---
    const int mrow = lane >> 2;
    const int ncol = (lane & 3) * 2;
    #pragma unroll
    for (int tn = 0; tn < 6; tn++) {
        int n = n0 + wn + tn * 8 + ncol;
        if (n < NW) {
            float2 bb = *(const float2*)(d_bpack + n);
            #pragma unroll
            for (int tm = 0; tm < 4; tm++) {
                size_t m = (size_t)(M0 + wm + tm * 16 + mrow);
                float2 v0 = make_float2(d[tm][tn][0] + bb.x, d[tm][tn][1] + bb.y);
                float2 v1 = make_float2(d[tm][tn][2] + bb.x, d[tm][tn][3] + bb.y);
                *(float2*)(d_pre + m * NW + n)       = v0;
                *(float2*)(d_pre + (m + 8) * NW + n) = v1;
            }
        }
    }
}

// ---------------- phase 2: sequential scan, 1 block (64 thr) per 2 batch elements ----
// GEMV fully in packed f32x2: h stored as (b0,b1) u64 pairs; U broadcast via alu-pipe
// dup (dual-issues against the fma pipe). Per-lane rounding identical to scalar.
__global__ __launch_bounds__(64, 6) void recurrent_kernel(
    const float* __restrict__ U_a, const float* __restrict__ b_a,
    const float* __restrict__ W_p, const float* __restrict__ b_p,
    const float* __restrict__ fc_w, const float* __restrict__ fc_b,
    float* __restrict__ out)
{
    const int j  = threadIdx.x;
    const int b0 = blockIdx.x * NB;

    __shared__ __align__(16) u64 sh_hP[HID];   // (h_b0, h_b1) pairs
    __shared__ u64 sh_freP[FREQ];
    __shared__ float sh_ct[FREQ], sh_st[FREQ];
    __shared__ float2 sh_red[2];

    const float4* U0 = (const float4*)d_Upk;
    const float4* U1 = (const float4*)d_Upk + 1024;
    const float4* U2 = (const float4*)d_Upk + 2048;
    const float4* U3 = (const float4*)d_Upk + 3072;
    const float4* UF = (const float4*)d_Ufpk;
    const ulonglong2* HP = (const ulonglong2*)sh_hP;

    u64 SreP[FREQ], SimP[FREQ];
    #pragma unroll
    for (int f = 0; f < FREQ; f++) { SreP[f] = 0ull; SimP[f] = 0ull; }

    float ua[FREQ];
    #pragma unroll
    for (int f = 0; f < FREQ; f++) ua[f] = U_a[f];
    const float ba = b_a[j];

    sh_hP[j] = 0ull;
    __syncthreads();

    float hn0 = 0.f, hn1 = 0.f;

    for (int t = 0; t < TSTEPS; t++) {
        const float* r = d_pre + ((size_t)t * BSZ + b0) * NW;
        float pi0 = r[j],        pi1 = r[NW + j];
        float ps0 = r[64 + j],   ps1 = r[NW + 64 + j];
        float pc0 = r[138 + j],  pc1 = r[NW + 138 + j];
        float po0 = r[202 + j],  po1 = r[NW + 202 + j];

        u64 aiP = 0ull, asP = 0ull, acP = 0ull, aoP = 0ull;

        #pragma unroll
        for (int k4 = 0; k4 < 16; k4++) {
            ulonglong2 h01 = HP[2 * k4];
            ulonglong2 h23 = HP[2 * k4 + 1];
            float4 u;
            u = U0[k4 * 64 + j];
            aiP = fma2(h01.x, dup2f(u.x), aiP); aiP = fma2(h01.y, dup2f(u.y), aiP);
            aiP = fma2(h23.x, dup2f(u.z), aiP); aiP = fma2(h23.y, dup2f(u.w), aiP);
            u = U1[k4 * 64 + j];
            asP = fma2(h01.x, dup2f(u.x), asP); asP = fma2(h01.y, dup2f(u.y), asP);
            asP = fma2(h23.x, dup2f(u.z), asP); asP = fma2(h23.y, dup2f(u.w), asP);
            u = U2[k4 * 64 + j];
            acP = fma2(h01.x, dup2f(u.x), acP); acP = fma2(h01.y, dup2f(u.y), acP);
            acP = fma2(h23.x, dup2f(u.z), acP); acP = fma2(h23.y, dup2f(u.w), acP);
            u = U3[k4 * 64 + j];
            aoP = fma2(h01.x, dup2f(u.x), aoP); aoP = fma2(h01.y, dup2f(u.y), aoP);
            aoP = fma2(h23.x, dup2f(u.z), aoP); aoP = fma2(h23.y, dup2f(u.w), aoP);
        }

        if (j < FREQ) {
            float pf0 = r[128 + j], pf1 = r[NW + 128 + j];
            u64 afP = 0ull;
            #pragma unroll
            for (int k4 = 0; k4 < 16; k4++) {
                ulonglong2 h01 = HP[2 * k4];
                ulonglong2 h23 = HP[2 * k4 + 1];
                float4 u = UF[k4 * FREQ + j];
                afP = fma2(h01.x, dup2f(u.x), afP); afP = fma2(h01.y, dup2f(u.y), afP);
                afP = fma2(h23.x, dup2f(u.z), afP); afP = fma2(h23.y, dup2f(u.w), afP);
            }
            float2 fa = unpack2f(afP);
            sh_freP[j] = pack2f(hsig(pf0 + fa.x), hsig(pf1 + fa.y));
            sh_ct[j] = d_cosT[t * FREQ + j];
            sh_st[j] = d_sinT[t * FREQ + j];
        }

        float2 ai = unpack2f(aiP), as = unpack2f(asP);
        float2 ac = unpack2f(acP), ao = unpack2f(aoP);
        float gi0 = hsig(pi0 + ai.x), gi1 = hsig(pi1 + ai.y);
        float gs0 = hsig(ps0 + as.x), gs1 = hsig(ps1 + as.y);
        float cc0 = gi0 * tanhf(pc0 + ac.x), cc1 = gi1 * tanhf(pc1 + ac.y);
        float go0 = hsig(po0 + ao.x), go1 = hsig(po1 + ao.y);

        __syncthreads();   // A: sh_freP/ct/st visible; all sh_hP reads done

        u64 ccP = pack2f(cc0, cc1);
        u64 gsP = pack2f(gs0, gs1);
        u64 aaP = pack2f(ba, ba);
        #pragma unroll
        for (int f = 0; f < FREQ; f++) {
            u64 ctd = dup2f(sh_ct[f]);
            u64 std = dup2f(sh_st[f]);
            u64 frP = mul2(gsP, sh_freP[f]);
            SreP[f] = fma2(frP, SreP[f], mul2(ccP, ctd));
            SimP[f] = fma2(frP, SimP[f], mul2(ccP, std));
            u64 ampP = fma2(SimP[f], SimP[f], mul2(SreP[f], SreP[f]));
            aaP = fma2(ampP, dup2f(ua[f]), aaP);
        }

        float2 a2 = unpack2f(aaP);
        hn0 = go0 * tanhf(a2.x);
        hn1 = go1 * tanhf(a2.y);
        sh_hP[j] = pack2f(hn0, hn1);   // safe: reads happened before barrier A
        __syncthreads();               // B: h(t+1) visible
    }

    float vv = 0.f;
    #pragma unroll
    for (int o = 0; o < OUTD; o++) vv = fmaf(W_p[j * OUTD + o], fc_w[o], vv);
    u64 pP = mul2(pack2f(hn0, hn1), dup2f(vv));
    #pragma unroll
    for (int off = 16; off > 0; off >>= 1)
        pP = add2(pP, __shfl_down_sync(0xffffffffu, pP, off));
    if ((j & 31) == 0) sh_red[j >> 5] = unpack2f(pP);
    __syncthreads();
    if (j == 0) {
        float s0 = fc_b[0];
        #pragma unroll
        for (int o = 0; o < OUTD; o++) s0 = fmaf(b_p[o], fc_w[o], s0);
        out[b0 + 0] = s0 + sh_red[0].x + sh_red[1].x;
        out[b0 + 1] = s0 + sh_red[0].y + sh_red[1].y;
    }
}

extern "C" void kernel_launch(void* const* d_in, const int* in_sizes, int n_in,
                              void* d_out, int out_size)
{
    const float* g1    = (const float*)d_in[0];
    const float* W_i   = (const float*)d_in[1];
    const float* U_i   = (const float*)d_in[2];
    const float* b_i   = (const float*)d_in[3];
    const float* W_ste = (const float*)d_in[4];
    const float* U_ste = (const float*)d_in[5];
    const float* b_ste = (const float*)d_in[6];
    const float* W_fre = (const float*)d_in[7];
    const float* U_fre = (const float*)d_in[8];
    const float* b_fre = (const float*)d_in[9];
    const float* W_c   = (const float*)d_in[10];
    const float* U_c   = (const float*)d_in[11];
    const float* b_c   = (const float*)d_in[12];
    const float* W_o   = (const float*)d_in[13];
    const float* U_o   = (const float*)d_in[14];
    const float* b_o   = (const float*)d_in[15];
    const float* U_a   = (const float*)d_in[16];
    const float* b_a   = (const float*)d_in[17];
    const float* W_p   = (const float*)d_in[18];
    const float* b_p   = (const float*)d_in[19];
    const float* fc_w  = (const float*)d_in[20];
    const float* fc_b  = (const float*)d_in[21];

    pack_w_kernel<<<NPAD, 256>>>(W_i, b_i, W_ste, b_ste, W_fre, b_fre,
                                 W_c, b_c, W_o, b_o);
    pack_u_kernel<<<16, 256>>>(U_i, U_ste, U_c, U_o, U_fre);
    trig_kernel<<<5, 256>>>();
    gemm_mma_kernel<<<dim3(3, 1024), 128>>>(g1);
    recurrent_kernel<<<BSZ / NB, HID>>>(U_a, b_a, W_p, b_p, fc_w, fc_b,
                                        (float*)d_out);
}

// round 8
// speedup vs baseline: 10.9836x; 1.4229x over previous
#include <cuda_runtime.h>
#include <cuda_bf16.h>
#include <cstdint>

#define BSZ    1024
#define TSTEPS 128
#define INDIM  256
#define HID    64
#define FREQ   10
#define OUTD   16
#define NW     266     // packed gate cols: i(64) | ste(64) | fre(10) | c(64) | o(64)
#define NPAD   288     // padded N: 3 tiles of 96
#define MROWS  (BSZ * TSTEPS)
#define NB     2       // batch elements per recurrent block

typedef unsigned long long u64;

// ----------------- device globals (no runtime allocation) -----------------
__device__ __align__(16) float d_pre[(size_t)MROWS * NW];      // (t*1024+b, 266) fp32
__device__ __align__(16) __nv_bfloat16 d_Ahi[(size_t)MROWS * INDIM];
__device__ __align__(16) __nv_bfloat16 d_Alo[(size_t)MROWS * INDIM];
__device__ __align__(16) __nv_bfloat16 d_Bhi[NPAD * INDIM];    // [n][k] bf16 hi
__device__ __align__(16) __nv_bfloat16 d_Blo[NPAD * INDIM];    // [n][k] bf16 lo
__device__ __align__(8)  float d_bpack[NPAD];
__device__ float d_Upk[4 * HID * HID];                          // interleaved [m][k4][j][kk]
__device__ float d_Ufpk[16 * FREQ * 4];
__device__ float d_cosT[TSTEPS * FREQ];
__device__ float d_sinT[TSTEPS * FREQ];

__device__ __forceinline__ float hsig(float x) {
    return fminf(fmaxf(x * (1.0f / 6.0f) + 0.5f, 0.0f), 1.0f);
}

// ---- packed f32x2 helpers (state update only) ----
__device__ __forceinline__ u64 pack2f(float lo, float hi) {
    u64 r; asm("mov.b64 %0, {%1, %2};" : "=l"(r) : "f"(lo), "f"(hi)); return r;
}
__device__ __forceinline__ float2 unpack2f(u64 v) {
    float2 r; asm("mov.b64 {%0, %1}, %2;" : "=f"(r.x), "=f"(r.y) : "l"(v)); return r;
}
__device__ __forceinline__ u64 dup2f(float x) { return pack2f(x, x); }
__device__ __forceinline__ u64 fma2(u64 a, u64 b, u64 c) {
    u64 d; asm("fma.rn.f32x2 %0, %1, %2, %3;" : "=l"(d) : "l"(a), "l"(b), "l"(c)); return d;
}
__device__ __forceinline__ u64 mul2(u64 a, u64 b) {
    u64 d; asm("mul.rn.f32x2 %0, %1, %2;" : "=l"(d) : "l"(a), "l"(b)); return d;
}
__device__ __forceinline__ u64 add2(u64 a, u64 b) {
    u64 d; asm("add.rn.f32x2 %0, %1, %2;" : "=l"(d) : "l"(a), "l"(b)); return d;
}

__device__ __forceinline__ uint32_t smem_u32(const void* p) {
    uint32_t a;
    asm("{ .reg .u64 t; cvta.to.shared.u64 t, %1; cvt.u32.u64 %0, t; }" : "=r"(a) : "l"(p));
    return a;
}

// ---- base-ISA async copy / mma helpers (no sm_103a-only features) ----
__device__ __forceinline__ void cp16(uint32_t dst, const void* src) {
    asm volatile("cp.async.cg.shared.global [%0], [%1], 16;" :: "r"(dst), "l"(src));
}
#define CP_COMMIT()  asm volatile("cp.async.commit_group;" ::: "memory")
#define CP_WAIT(N)   asm volatile("cp.async.wait_group %0;" :: "n"(N) : "memory")

#define LDSM4(r0, r1, r2, r3, addr) \
    asm volatile("ldmatrix.sync.aligned.m8n8.x4.shared.b16 {%0,%1,%2,%3}, [%4];" \
        : "=r"(r0), "=r"(r1), "=r"(r2), "=r"(r3) : "r"(addr))

#define MMA16816(d, a, b0, b1) \
    asm volatile("mma.sync.aligned.m16n8k16.row.col.f32.bf16.bf16.f32 " \
        "{%0,%1,%2,%3}, {%4,%5,%6,%7}, {%8,%9}, {%0,%1,%2,%3};" \
        : "+f"((d)[0]), "+f"((d)[1]), "+f"((d)[2]), "+f"((d)[3]) \
        : "r"((a)[0]), "r"((a)[1]), "r"((a)[2]), "r"((a)[3]), "r"(b0), "r"(b1))

// ---------------- g1 fp32 -> (Ahi, Alo) bf16, transposed to m = t*1024+b ----------
__global__ __launch_bounds__(256) void conv_kernel(const float* __restrict__ g1)
{
    int idx = blockIdx.x * 256 + threadIdx.x;
    int row = idx >> 6, g = idx & 63;              // row = b*128 + t
    int b = row >> 7, t = row & 127;
    float4 v = *(const float4*)(g1 + (size_t)row * INDIM + g * 4);
    size_t m = (size_t)t * BSZ + b;
    float xs[4] = {v.x, v.y, v.z, v.w};
    __nv_bfloat16 h[4], l[4];
    #pragma unroll
    for (int i = 0; i < 4; i++) {
        h[i] = __float2bfloat16(xs[i]);
        l[i] = __float2bfloat16(xs[i] - __bfloat162float(h[i]));
    }
    uint32_t hi01 = (uint32_t)__bfloat16_as_ushort(h[0]) | ((uint32_t)__bfloat16_as_ushort(h[1]) << 16);
    uint32_t hi23 = (uint32_t)__bfloat16_as_ushort(h[2]) | ((uint32_t)__bfloat16_as_ushort(h[3]) << 16);
    uint32_t lo01 = (uint32_t)__bfloat16_as_ushort(l[0]) | ((uint32_t)__bfloat16_as_ushort(l[1]) << 16);
    uint32_t lo23 = (uint32_t)__bfloat16_as_ushort(l[2]) | ((uint32_t)__bfloat16_as_ushort(l[3]) << 16);
    *(uint2*)(d_Ahi + m * INDIM + g * 4) = make_uint2(hi01, hi23);
    *(uint2*)(d_Alo + m * INDIM + g * 4) = make_uint2(lo01, lo23);
}

// ---------------- pack W_* -> Bhi/Blo [288][256] bf16 (+ biases fp32) ---------------
__global__ void pack_w_kernel(const float* __restrict__ W_i,  const float* __restrict__ b_i,
                              const float* __restrict__ W_ste,const float* __restrict__ b_ste,
                              const float* __restrict__ W_fre,const float* __restrict__ b_fre,
                              const float* __restrict__ W_c,  const float* __restrict__ b_c,
                              const float* __restrict__ W_o,  const float* __restrict__ b_o)
{
    int n = blockIdx.x;      // 0..287
    int k = threadIdx.x;     // 0..255
    float w = 0.f, bias = 0.f;
    if (n < 64)       { w = W_i  [k * HID  + n];         bias = b_i  [n]; }
    else if (n < 128) { w = W_ste[k * HID  + (n - 64)];  bias = b_ste[n - 64]; }
    else if (n < 138) { w = W_fre[k * FREQ + (n - 128)]; bias = b_fre[n - 128]; }
    else if (n < 202) { w = W_c  [k * HID  + (n - 138)]; bias = b_c  [n - 138]; }
    else if (n < 266) { w = W_o  [k * HID  + (n - 202)]; bias = b_o  [n - 202]; }
    __nv_bfloat16 h = __float2bfloat16(w);
    __nv_bfloat16 l = __float2bfloat16(w - __bfloat162float(h));
    d_Bhi[n * INDIM + k] = h;
    d_Blo[n * INDIM + k] = l;
    if (k == 0) d_bpack[n] = bias;
}

// -------- interleave U so thread j's float4 = U[4*k4 .. 4*k4+3][j] (warp = 512B) ----
__global__ void pack_u_kernel(const float* __restrict__ U_i, const float* __restrict__ U_ste,
                              const float* __restrict__ U_c, const float* __restrict__ U_o,
                              const float* __restrict__ U_fre)
{
    int idx = blockIdx.x * blockDim.x + threadIdx.x;   // 16 x 256 = 4096
    int k4 = idx >> 8, j = (idx >> 2) & 63, kk = idx & 3;
    int k = 4 * k4 + kk;
    d_Upk[0 * 4096 + idx] = U_i  [k * HID + j];
    d_Upk[1 * 4096 + idx] = U_ste[k * HID + j];
    d_Upk[2 * 4096 + idx] = U_c  [k * HID + j];
    d_Upk[3 * 4096 + idx] = U_o  [k * HID + j];
    if (idx < 16 * FREQ * 4) {
        int fk4 = idx / (FREQ * 4), rr = idx % (FREQ * 4);
        int fj = rr >> 2, fkk = rr & 3;
        d_Ufpk[idx] = U_fre[(4 * fk4 + fkk) * FREQ + fj];
    }
}

// ---------------- trig table, replicating reference fp32 arithmetic ------------------
__global__ void trig_kernel()
{
    int idx = blockIdx.x * blockDim.x + threadIdx.x;   // TSTEPS*FREQ = 1280
    if (idx < TSTEPS * FREQ) {
        int t = idx / FREQ, f = idx % FREQ;
        float fr = (float)f / 10.0f;
        float omega = (6.28318530717958647692f * (float)(t + 1)) * fr;
        d_cosT[idx] = cosf(omega);
        d_sinT[idx] = sinf(omega);
    }
}

// ---------------- phase 1: mma.sync bf16 hi/lo 3-term GEMM, cp.async 2-stage --------
// Block 128 thr / 4 warps; tile M=128 x N=96; warp tile 64x48 (4x6 m16n8k16).
// smem rows stride 40 bf16 (80B, conflict-free ldmatrix). Double-buffered stages.
#define SA_HI 0
#define SA_LO 5120
#define SB_HI 10240
#define SB_LO 14080
#define STAGE_ELEMS 17920
#define STAGE_BYTES (STAGE_ELEMS * 2)
#define SMEM_GEMM   (2 * STAGE_BYTES)   // 71680 B

__device__ __forceinline__ void issue_stage(__nv_bfloat16* sm, int s, int kc,
                                            size_t M0, int n0, int tid)
{
    __nv_bfloat16* base = sm + s * STAGE_ELEMS;
    #pragma unroll
    for (int l = 0; l < 4; l++) {            // A: 512 chunks (hi+lo pairs)
        int idx = tid + l * 128;
        int row = idx >> 2, g = idx & 3;
        size_t goff = (M0 + row) * INDIM + kc * 32 + g * 8;
        cp16(smem_u32(base + SA_HI + row * 40 + g * 8), d_Ahi + goff);
        cp16(smem_u32(base + SA_LO + row * 40 + g * 8), d_Alo + goff);
    }
    #pragma unroll
    for (int l = 0; l < 3; l++) {            // B: 384 chunks (hi+lo pairs)
        int idx = tid + l * 128;
        int row = idx >> 2, g = idx & 3;
        size_t goff = (size_t)(n0 + row) * INDIM + kc * 32 + g * 8;
        cp16(smem_u32(base + SB_HI + row * 40 + g * 8), d_Bhi + goff);
        cp16(smem_u32(base + SB_LO + row * 40 + g * 8), d_Blo + goff);
    }
    CP_COMMIT();
}

__global__ __launch_bounds__(128) void gemm_mma_kernel()
{
    extern __shared__ __align__(16) __nv_bfloat16 sm[];

    const int tid  = threadIdx.x;
    const int lane = tid & 31;
    const int wid  = tid >> 5;
    const int n0   = blockIdx.x * 96;
    const size_t M0 = (size_t)blockIdx.y * 128;
    const int wm = (wid & 1) * 64;
    const int wn = (wid >> 1) * 48;

    float d[4][6][4];
    #pragma unroll
    for (int tm = 0; tm < 4; tm++)
        #pragma unroll
        for (int tn = 0; tn < 6; tn++)
            #pragma unroll
            for (int q = 0; q < 4; q++) d[tm][tn][q] = 0.f;

    // ldmatrix lane-relative byte offsets (within a stage)
    const int rowA = wm + (lane & 15);
    const int colA = (lane >> 4) * 8;
    const uint32_t relAhi = (uint32_t)(SA_HI + rowA * 40 + colA) * 2;
    const uint32_t relAlo = (uint32_t)(SA_LO + rowA * 40 + colA) * 2;
    const int rowB = wn + ((lane >> 4) * 8) + (lane & 7);
    const int colB = ((lane >> 3) & 1) * 8;
    const uint32_t relBhi = (uint32_t)(SB_HI + rowB * 40 + colB) * 2;
    const uint32_t relBlo = (uint32_t)(SB_LO + rowB * 40 + colB) * 2;
    const uint32_t smbase = smem_u32(sm);

    issue_stage(sm, 0, 0, M0, n0, tid);

    for (int kc = 0; kc < 8; kc++) {
        int cur = kc & 1;
        if (kc < 7) {
            issue_stage(sm, cur ^ 1, kc + 1, M0, n0, tid);
            CP_WAIT(1);
        } else {
            CP_WAIT(0);
        }
        __syncthreads();

        uint32_t sb = smbase + (uint32_t)cur * STAGE_BYTES;
        #pragma unroll
        for (int ks = 0; ks < 2; ks++) {
            uint32_t ah[4][4], al[4][4], bh[3][4], bl[3][4];
            #pragma unroll
            for (int tm = 0; tm < 4; tm++) {
                uint32_t off = (uint32_t)(tm * 16 * 40 + ks * 16) * 2;
                LDSM4(ah[tm][0], ah[tm][1], ah[tm][2], ah[tm][3], sb + relAhi + off);
                LDSM4(al[tm][0], al[tm][1], al[tm][2], al[tm][3], sb + relAlo + off);
            }
            #pragma unroll
            for (int jB = 0; jB < 3; jB++) {
                uint32_t off = (uint32_t)(jB * 16 * 40 + ks * 16) * 2;
                LDSM4(bh[jB][0], bh[jB][1], bh[jB][2], bh[jB][3], sb + relBhi + off);
                LDSM4(bl[jB][0], bl[jB][1], bl[jB][2], bl[jB][3], sb + relBlo + off);
            }
            #pragma unroll
            for (int tm = 0; tm < 4; tm++)
                #pragma unroll
                for (int tn = 0; tn < 6; tn++) {
                    int jB = tn >> 1, hh = (tn & 1) * 2;
                    MMA16816(d[tm][tn], ah[tm], bh[jB][hh], bh[jB][hh + 1]);
                    MMA16816(d[tm][tn], ah[tm], bl[jB][hh], bl[jB][hh + 1]);
                    MMA16816(d[tm][tn], al[tm], bh[jB][hh], bh[jB][hh + 1]);
                }
        }
        __syncthreads();   // all fragment reads of `cur` done before kc+2 overwrites it
    }

    // --- epilogue: write d_pre with bias, predicated at n < 266 ---
    const int mrow = lane >> 2;
    const int ncol = (lane & 3) * 2;
    #pragma unroll
    for (int tn = 0; tn < 6; tn++) {
        int n = n0 + wn + tn * 8 + ncol;
        if (n < NW) {
            float2 bb = *(const float2*)(d_bpack + n);
            #pragma unroll
            for (int tm = 0; tm < 4; tm++) {
                size_t m = M0 + wm + tm * 16 + mrow;
                float2 v0 = make_float2(d[tm][tn][0] + bb.x, d[tm][tn][1] + bb.y);
                float2 v1 = make_float2(d[tm][tn][2] + bb.x, d[tm][tn][3] + bb.y);
                *(float2*)(d_pre + m * NW + n)       = v0;
                *(float2*)(d_pre + (m + 8) * NW + n) = v1;
            }
        }
    }
}

// ---------------- phase 2: sequential scan (R5 scalar-FFMA version, proven) ---------
__global__ __launch_bounds__(64, 6) void recurrent_kernel(
    const float* __restrict__ U_a, const float* __restrict__ b_a,
    const float* __restrict__ W_p, const float* __restrict__ b_p,
    const float* __restrict__ fc_w, const float* __restrict__ fc_b,
    float* __restrict__ out)
{
    const int j  = threadIdx.x;
    const int b0 = blockIdx.x * NB;

    __shared__ __align__(16) float sh_h0[HID];
    __shared__ __align__(16) float sh_h1[HID];
    __shared__ u64 sh_freP[FREQ];
    __shared__ float sh_ct[FREQ], sh_st[FREQ];
    __shared__ float2 sh_red[2];

    const float4* U0 = (const float4*)d_Upk;
    const float4* U1 = (const float4*)d_Upk + 1024;
    const float4* U2 = (const float4*)d_Upk + 2048;
    const float4* U3 = (const float4*)d_Upk + 3072;
    const float4* UF = (const float4*)d_Ufpk;
    const float4* H0 = (const float4*)sh_h0;
    const float4* H1 = (const float4*)sh_h1;

    u64 SreP[FREQ], SimP[FREQ];
    #pragma unroll
    for (int f = 0; f < FREQ; f++) { SreP[f] = 0ull; SimP[f] = 0ull; }

    float ua[FREQ];
    #pragma unroll
    for (int f = 0; f < FREQ; f++) ua[f] = U_a[f];
    const float ba = b_a[j];

    sh_h0[j] = 0.f; sh_h1[j] = 0.f;
    __syncthreads();

    float hn0 = 0.f, hn1 = 0.f;

    for (int t = 0; t < TSTEPS; t++) {
        const float* r = d_pre + ((size_t)t * BSZ + b0) * NW;
        float pi0 = r[j],        pi1 = r[NW + j];
        float ps0 = r[64 + j],   ps1 = r[NW + 64 + j];
        float pc0 = r[138 + j],  pc1 = r[NW + 138 + j];
        float po0 = r[202 + j],  po1 = r[NW + 202 + j];

        float ai0 = 0.f, ai1 = 0.f, as0 = 0.f, as1 = 0.f;
        float ac0 = 0.f, ac1 = 0.f, ao0 = 0.f, ao1 = 0.f;

        #pragma unroll
        for (int k4 = 0; k4 < 16; k4++) {
            float4 h0 = H0[k4];
            float4 h1 = H1[k4];
            float4 u;
            u = U0[k4 * 64 + j];
            ai0 = fmaf(h0.x,u.x,ai0); ai0 = fmaf(h0.y,u.y,ai0);
            ai0 = fmaf(h0.z,u.z,ai0); ai0 = fmaf(h0.w,u.w,ai0);
            ai1 = fmaf(h1.x,u.x,ai1); ai1 = fmaf(h1.y,u.y,ai1);
            ai1 = fmaf(h1.z,u.z,ai1); ai1 = fmaf(h1.w,u.w,ai1);
            u = U1[k4 * 64 + j];
            as0 = fmaf(h0.x,u.x,as0); as0 = fmaf(h0.y,u.y,as0);
            as0 = fmaf(h0.z,u.z,as0); as0 = fmaf(h0.w,u.w,as0);
            as1 = fmaf(h1.x,u.x,as1); as1 = fmaf(h1.y,u.y,as1);
            as1 = fmaf(h1.z,u.z,as1); as1 = fmaf(h1.w,u.w,as1);
            u = U2[k4 * 64 + j];
            ac0 = fmaf(h0.x,u.x,ac0); ac0 = fmaf(h0.y,u.y,ac0);
            ac0 = fmaf(h0.z,u.z,ac0); ac0 = fmaf(h0.w,u.w,ac0);
            ac1 = fmaf(h1.x,u.x,ac1); ac1 = fmaf(h1.y,u.y,ac1);
            ac1 = fmaf(h1.z,u.z,ac1); ac1 = fmaf(h1.w,u.w,ac1);
            u = U3[k4 * 64 + j];
            ao0 = fmaf(h0.x,u.x,ao0); ao0 = fmaf(h0.y,u.y,ao0);
            ao0 = fmaf(h0.z,u.z,ao0); ao0 = fmaf(h0.w,u.w,ao0);
            ao1 = fmaf(h1.x,u.x,ao1); ao1 = fmaf(h1.y,u.y,ao1);
            ao1 = fmaf(h1.z,u.z,ao1); ao1 = fmaf(h1.w,u.w,ao1);
        }

        if (j < FREQ) {
            float pf0 = r[128 + j], pf1 = r[NW + 128 + j];
            float af0 = 0.f, af1 = 0.f;
            #pragma unroll
            for (int k4 = 0; k4 < 16; k4++) {
                float4 h0 = H0[k4];
                float4 h1 = H1[k4];
                float4 u = UF[k4 * FREQ + j];
                af0 = fmaf(h0.x,u.x,af0); af0 = fmaf(h0.y,u.y,af0);
                af0 = fmaf(h0.z,u.z,af0); af0 = fmaf(h0.w,u.w,af0);
                af1 = fmaf(h1.x,u.x,af1); af1 = fmaf(h1.y,u.y,af1);
                af1 = fmaf(h1.z,u.z,af1); af1 = fmaf(h1.w,u.w,af1);
            }
            sh_freP[j] = pack2f(hsig(pf0 + af0), hsig(pf1 + af1));
            sh_ct[j] = d_cosT[t * FREQ + j];
            sh_st[j] = d_sinT[t * FREQ + j];
        }

        float gi0 = hsig(pi0 + ai0), gi1 = hsig(pi1 + ai1);
        float gs0 = hsig(ps0 + as0), gs1 = hsig(ps1 + as1);
        float cc0 = gi0 * tanhf(pc0 + ac0), cc1 = gi1 * tanhf(pc1 + ac1);
        float go0 = hsig(po0 + ao0), go1 = hsig(po1 + ao1);

        __syncthreads();   // A: sh_freP/ct/st visible; all sh_h reads done

        u64 ccP = pack2f(cc0, cc1);
        u64 gsP = pack2f(gs0, gs1);
        u64 aaP = pack2f(ba, ba);
        #pragma unroll
        for (int f = 0; f < FREQ; f++) {
            u64 ctd = dup2f(sh_ct[f]);
            u64 std = dup2f(sh_st[f]);
            u64 frP = mul2(gsP, sh_freP[f]);
            SreP[f] = fma2(frP, SreP[f], mul2(ccP, ctd));
            SimP[f] = fma2(frP, SimP[f], mul2(ccP, std));
            u64 ampP = fma2(SimP[f], SimP[f], mul2(SreP[f], SreP[f]));
            aaP = fma2(ampP, dup2f(ua[f]), aaP);
        }

        float2 a2 = unpack2f(aaP);
        hn0 = go0 * tanhf(a2.x);
        hn1 = go1 * tanhf(a2.y);
        sh_h0[j] = hn0;    // safe: all sh_h reads happened before barrier A
        sh_h1[j] = hn1;
        __syncthreads();   // B: h(t+1) visible for next iteration
    }

    float vv = 0.f;
    #pragma unroll
    for (int o = 0; o < OUTD; o++) vv = fmaf(W_p[j * OUTD + o], fc_w[o], vv);
    u64 pP = mul2(pack2f(hn0, hn1), dup2f(vv));
    #pragma unroll
    for (int off = 16; off > 0; off >>= 1)
        pP = add2(pP, __shfl_down_sync(0xffffffffu, pP, off));
    if ((j & 31) == 0) sh_red[j >> 5] = unpack2f(pP);
    __syncthreads();
    if (j == 0) {
        float s0 = fc_b[0];
        #pragma unroll
        for (int o = 0; o < OUTD; o++) s0 = fmaf(b_p[o], fc_w[o], s0);
        out[b0 + 0] = s0 + sh_red[0].x + sh_red[1].x;
        out[b0 + 1] = s0 + sh_red[0].y + sh_red[1].y;
    }
}

extern "C" void kernel_launch(void* const* d_in, const int* in_sizes, int n_in,
                              void* d_out, int out_size)
{
    const float* g1    = (const float*)d_in[0];
    const float* W_i   = (const float*)d_in[1];
    const float* U_i   = (const float*)d_in[2];
    const float* b_i   = (const float*)d_in[3];
    const float* W_ste = (const float*)d_in[4];
    const float* U_ste = (const float*)d_in[5];
    const float* b_ste = (const float*)d_in[6];
    const float* W_fre = (const float*)d_in[7];
    const float* U_fre = (const float*)d_in[8];
    const float* b_fre = (const float*)d_in[9];
    const float* W_c   = (const float*)d_in[10];
    const float* U_c   = (const float*)d_in[11];
    const float* b_c   = (const float*)d_in[12];
    const float* W_o   = (const float*)d_in[13];
    const float* U_o   = (const float*)d_in[14];
    const float* b_o   = (const float*)d_in[15];
    const float* U_a   = (const float*)d_in[16];
    const float* b_a   = (const float*)d_in[17];
    const float* W_p   = (const float*)d_in[18];
    const float* b_p   = (const float*)d_in[19];
    const float* fc_w  = (const float*)d_in[20];
    const float* fc_b  = (const float*)d_in[21];

    // host-side attribute set: not a stream op, capture-transparent, deterministic
    cudaFuncSetAttribute(gemm_mma_kernel,
                         cudaFuncAttributeMaxDynamicSharedMemorySize, SMEM_GEMM);

    conv_kernel<<<MROWS * 64 / 256, 256>>>(g1);
    pack_w_kernel<<<NPAD, 256>>>(W_i, b_i, W_ste, b_ste, W_fre, b_fre,
                                 W_c, b_c, W_o, b_o);
    pack_u_kernel<<<16, 256>>>(U_i, U_ste, U_c, U_o, U_fre);
    trig_kernel<<<5, 256>>>();
    gemm_mma_kernel<<<dim3(3, 1024), 128, SMEM_GEMM>>>();
    recurrent_kernel<<<BSZ / NB, HID>>>(U_a, b_a, W_p, b_p, fc_w, fc_b,
                                        (float*)d_out);
}